// round 5
// baseline (speedup 1.0000x reference)
#include <cuda_runtime.h>

// ---------------------------------------------------------------------------
// One-pole IIR scan:  out_t = b0*x_t + s_{t-1};  s_t = b1*x_t + a*out_t
// State-only form:    s_t = k*x_t + a*s_{t-1},   k = b1 + a*b0  (a = clamp(a1))
//
// Single fused pass, chunked over time. Each chunk warms up its state from
// zero W steps early (W chosen on-device so |a|^W < 2^-39, below fp32
// resolution; W clamps to the chunk start, so exact for any |a| — chunk 0
// always uses the true initial state). Grid is sized to EXACTLY 4 blocks/SM
// (592 blocks on 148 SMs) to eliminate the load-imbalance tail.
// ---------------------------------------------------------------------------

#define NUM_SMS 148
#define BLOCKS_PER_SM 4

__device__ __forceinline__ float clamp_a(float a) {
    return fminf(fmaxf(a, -1.0f), 1.0f);
}

__device__ __forceinline__ int warmup_len(float a, int t0) {
    float la = fabsf(a);
    int W;
    if (la >= 0.999999f) {
        W = t0;                          // exact: run from t=0
    } else if (la <= 1e-30f) {
        W = 2;
    } else {
        float w = ceilf(39.0f / (-__log2f(la)));
        W = (int)w + 1;
        if (W < 2) W = 2;
    }
    if (W > t0) W = t0;
    return W;
}

// ------------------------------ float2 path --------------------------------

__global__ void __launch_bounds__(128)
k_fused2(const float2* __restrict__ x,
         const float2* __restrict__ statep,
         const float* __restrict__ b0p,
         const float* __restrict__ b1p,
         const float* __restrict__ a1p,
         float2* __restrict__ out,
         float2* __restrict__ finalDst,   // may be null
         int T, int B2, int L) {
    int c2 = blockIdx.x * blockDim.x + threadIdx.x;
    if (c2 >= B2) return;
    int chunk = blockIdx.y;

    float a  = clamp_a(a1p[0]);
    float b0 = b0p[0];
    float k  = fmaf(a, b0, b1p[0]);      // k = b1 + a*b0

    int t0   = chunk * L;
    if (t0 >= T) return;
    int tend = t0 + L; if (tend > T) tend = T;

    int W = warmup_len(a, t0);
    int start = t0 - W;

    float2 s = (start == 0) ? statep[c2] : make_float2(0.f, 0.f);

    // --- warmup: state-only (no stores) ---
    {
        const float2* p = x + (long)start * B2 + c2;
        #pragma unroll 16
        for (int i = 0; i < W; i++) {
            float2 xv = p[(long)i * B2];
            s.x = fmaf(a, s.x, k * xv.x);
            s.y = fmaf(a, s.y, k * xv.y);
        }
    }

    // --- main: produce outputs; 1 dependent FMA per step per lane ---
    {
        const float2* pm = x + (long)t0 * B2 + c2;
        float2* po = out + (long)t0 * B2 + c2;
        int n = tend - t0;
        #pragma unroll 16
        for (int j = 0; j < n; j++) {
            float2 xv = pm[(long)j * B2];
            float2 o;
            o.x = fmaf(b0, xv.x, s.x);
            o.y = fmaf(b0, xv.y, s.y);
            __stcs(&po[(long)j * B2], o);
            s.x = fmaf(a, s.x, k * xv.x);   // s = k*x + a*s
            s.y = fmaf(a, s.y, k * xv.y);
        }
    }

    if (finalDst && tend == T) {
        finalDst[c2] = s;
    }
}

// ------------------------------ scalar path --------------------------------

__global__ void __launch_bounds__(128)
k_fused1(const float* __restrict__ x,
         const float* __restrict__ statep,
         const float* __restrict__ b0p,
         const float* __restrict__ b1p,
         const float* __restrict__ a1p,
         float* __restrict__ out,
         float* __restrict__ finalDst,
         int T, int B, int L) {
    int c = blockIdx.x * blockDim.x + threadIdx.x;
    if (c >= B) return;
    int chunk = blockIdx.y;

    float a  = clamp_a(a1p[0]);
    float b0 = b0p[0];
    float k  = fmaf(a, b0, b1p[0]);

    int t0   = chunk * L;
    if (t0 >= T) return;
    int tend = t0 + L; if (tend > T) tend = T;

    int W = warmup_len(a, t0);
    int start = t0 - W;
    float s = (start == 0) ? statep[c] : 0.0f;

    const float* p = x + (long)start * B + c;
    #pragma unroll 16
    for (int i = 0; i < W; i++) {
        s = fmaf(a, s, k * p[(long)i * B]);
    }

    const float* pm = x + (long)t0 * B + c;
    float* po = out + (long)t0 * B + c;
    int n = tend - t0;
    #pragma unroll 16
    for (int j = 0; j < n; j++) {
        float xv = pm[(long)j * B];
        float o  = fmaf(b0, xv, s);
        __stcs(&po[(long)j * B], o);
        s = fmaf(a, s, k * xv);
    }

    if (finalDst && tend == T) finalDst[c] = s;
}

// ---------------------------------------------------------------------------

extern "C" void kernel_launch(void* const* d_in, const int* in_sizes, int n_in,
                              void* d_out, int out_size) {
    const float* x     = (const float*)d_in[0];
    const float* state = (const float*)d_in[1];
    const float* b0    = (const float*)d_in[2];
    const float* b1    = (const float*)d_in[3];
    const float* a1    = (const float*)d_in[4];
    float* out = (float*)d_out;

    long TB = in_sizes[0];
    int  B  = in_sizes[1];
    int  T  = (int)(TB / B);

    bool writeFinal = ((long)out_size >= TB + B);
    float* finalDst = writeFinal ? (out + TB) : nullptr;

    const int TPB = 128;
    const int targetBlocks = NUM_SMS * BLOCKS_PER_SM;   // 592

    if ((B & 1) == 0) {
        int B2 = B >> 1;
        int xBlocks = (B2 + TPB - 1) / TPB;
        // chunks so that total blocks ~= targetBlocks (perfect 4/SM balance)
        int numChunks = targetBlocks / xBlocks;
        if (numChunks < 1) numChunks = 1;
        if (numChunks > T) numChunks = T;
        int L = (T + numChunks - 1) / numChunks;
        numChunks = (T + L - 1) / L;

        dim3 grid(xBlocks, numChunks);
        k_fused2<<<grid, TPB>>>((const float2*)x, (const float2*)state,
                                b0, b1, a1, (float2*)out,
                                (float2*)finalDst, T, B2, L);
    } else {
        int xBlocks = (B + TPB - 1) / TPB;
        int numChunks = targetBlocks / xBlocks;
        if (numChunks < 1) numChunks = 1;
        if (numChunks > T) numChunks = T;
        int L = (T + numChunks - 1) / numChunks;
        numChunks = (T + L - 1) / L;

        dim3 grid(xBlocks, numChunks);
        k_fused1<<<grid, TPB>>>(x, state, b0, b1, a1, out, finalDst, T, B, L);
    }
}

// round 7
// speedup vs baseline: 2.7186x; 2.7186x over previous
#include <cuda_runtime.h>

// ---------------------------------------------------------------------------
// One-pole IIR scan:  out_t = b0*x_t + s_{t-1};  s_t = b1*x_t + a*out_t
// State-only form:    s_t = k*x_t + a*s_{t-1},   k = b1 + a*b0  (a = clamp(a1))
//
// Single fused pass, chunked over time; each chunk warms its state up from
// zero W steps early (|a|^W < 2^-44, below fp32 resolution; W clamps to the
// chunk start so the result is exact for any |a|). Loads are EXPLICITLY
// batched 8-at-a-time into register arrays so the LSU holds 64 B/thread in
// flight (regs=32 previously capped this at ~4 loads). Grid = 592 blocks of
// 256 threads = exactly 4 blocks/SM on 148 SMs.
// ---------------------------------------------------------------------------

#define NUM_SMS 148

__device__ __forceinline__ float clamp_a(float a) {
    return fminf(fmaxf(a, -1.0f), 1.0f);
}

__device__ __forceinline__ int warmup_len(float a, int t0) {
    float la = fabsf(a);
    int W;
    if (la >= 0.999999f) {
        W = t0;                          // exact: run from t=0
    } else if (la <= 1e-30f) {
        W = 2;
    } else {
        float w = ceilf(44.0f / (-__log2f(la)));
        W = (int)w + 1;
        if (W < 2) W = 2;
    }
    if (W > t0) W = t0;
    return W;
}

// ------------------------------ float2 path --------------------------------

__global__ void __launch_bounds__(256, 4)
k_fused2(const float2* __restrict__ x,
         const float2* __restrict__ statep,
         const float* __restrict__ b0p,
         const float* __restrict__ b1p,
         const float* __restrict__ a1p,
         float2* __restrict__ out,
         float2* __restrict__ finalDst,   // may be null
         int T, int B2, int L) {
    int c2 = blockIdx.x * blockDim.x + threadIdx.x;
    if (c2 >= B2) return;
    int chunk = blockIdx.y;

    float a  = clamp_a(a1p[0]);
    float b0 = b0p[0];
    float k  = fmaf(a, b0, b1p[0]);      // k = b1 + a*b0

    int t0 = chunk * L;
    if (t0 >= T) return;
    int tend = t0 + L; if (tend > T) tend = T;

    int W = warmup_len(a, t0);
    int start = t0 - W;

    float2 s = (start == 0) ? statep[c2] : make_float2(0.f, 0.f);

    // --- warmup: state-only, batch-8 loads ---
    {
        const float2* p = x + (long)start * B2 + c2;
        int nw = t0 - start;
        int nw8 = nw & ~7;
        int i = 0;
        for (; i < nw8; i += 8) {
            float2 v[8];
            #pragma unroll
            for (int u = 0; u < 8; u++) v[u] = p[(long)(i + u) * B2];
            #pragma unroll
            for (int u = 0; u < 8; u++) {
                s.x = fmaf(a, s.x, k * v[u].x);
                s.y = fmaf(a, s.y, k * v[u].y);
            }
        }
        for (; i < nw; i++) {
            float2 v = p[(long)i * B2];
            s.x = fmaf(a, s.x, k * v.x);
            s.y = fmaf(a, s.y, k * v.y);
        }
    }

    // --- main: batch-8 load / compute / store ---
    {
        const float2* pm = x + (long)t0 * B2 + c2;
        float2* po = out + (long)t0 * B2 + c2;
        int n = tend - t0;
        int n8 = n & ~7;
        int j = 0;
        for (; j < n8; j += 8) {
            float2 v[8];
            #pragma unroll
            for (int u = 0; u < 8; u++) v[u] = pm[(long)(j + u) * B2];
            float2 o[8];
            #pragma unroll
            for (int u = 0; u < 8; u++) {
                o[u].x = fmaf(b0, v[u].x, s.x);
                o[u].y = fmaf(b0, v[u].y, s.y);
                s.x = fmaf(a, s.x, k * v[u].x);   // s = k*x + a*s
                s.y = fmaf(a, s.y, k * v[u].y);
            }
            float2* po8 = po + (long)j * B2;
            #pragma unroll
            for (int u = 0; u < 8; u++) {
                __stcs(po8, o[u]);
                po8 += B2;
            }
        }
        for (; j < n; j++) {
            float2 v = pm[(long)j * B2];
            float2 o;
            o.x = fmaf(b0, v.x, s.x);
            o.y = fmaf(b0, v.y, s.y);
            __stcs(&po[(long)j * B2], o);
            s.x = fmaf(a, s.x, k * v.x);
            s.y = fmaf(a, s.y, k * v.y);
        }
    }

    if (finalDst && tend == T) {
        finalDst[c2] = s;
    }
}

// ------------------------------ scalar path --------------------------------

__global__ void __launch_bounds__(256, 4)
k_fused1(const float* __restrict__ x,
         const float* __restrict__ statep,
         const float* __restrict__ b0p,
         const float* __restrict__ b1p,
         const float* __restrict__ a1p,
         float* __restrict__ out,
         float* __restrict__ finalDst,
         int T, int B, int L) {
    int c = blockIdx.x * blockDim.x + threadIdx.x;
    if (c >= B) return;
    int chunk = blockIdx.y;

    float a  = clamp_a(a1p[0]);
    float b0 = b0p[0];
    float k  = fmaf(a, b0, b1p[0]);

    int t0 = chunk * L;
    if (t0 >= T) return;
    int tend = t0 + L; if (tend > T) tend = T;

    int W = warmup_len(a, t0);
    int start = t0 - W;
    float s = (start == 0) ? statep[c] : 0.0f;

    {
        const float* p = x + (long)start * B + c;
        int nw = t0 - start;
        int nw8 = nw & ~7;
        int i = 0;
        for (; i < nw8; i += 8) {
            float v[8];
            #pragma unroll
            for (int u = 0; u < 8; u++) v[u] = p[(long)(i + u) * B];
            #pragma unroll
            for (int u = 0; u < 8; u++) s = fmaf(a, s, k * v[u]);
        }
        for (; i < nw; i++) s = fmaf(a, s, k * p[(long)i * B]);
    }

    {
        const float* pm = x + (long)t0 * B + c;
        float* po = out + (long)t0 * B + c;
        int n = tend - t0;
        int n8 = n & ~7;
        int j = 0;
        for (; j < n8; j += 8) {
            float v[8];
            #pragma unroll
            for (int u = 0; u < 8; u++) v[u] = pm[(long)(j + u) * B];
            float o[8];
            #pragma unroll
            for (int u = 0; u < 8; u++) {
                o[u] = fmaf(b0, v[u], s);
                s = fmaf(a, s, k * v[u]);
            }
            float* po8 = po + (long)j * B;
            #pragma unroll
            for (int u = 0; u < 8; u++) {
                __stcs(po8, o[u]);
                po8 += B;
            }
        }
        for (; j < n; j++) {
            float v = pm[(long)j * B];
            float o = fmaf(b0, v, s);
            __stcs(&po[(long)j * B], o);
            s = fmaf(a, s, k * v);
        }
    }

    if (finalDst && tend == T) finalDst[c] = s;
}

// ---------------------------------------------------------------------------

extern "C" void kernel_launch(void* const* d_in, const int* in_sizes, int n_in,
                              void* d_out, int out_size) {
    const float* x     = (const float*)d_in[0];
    const float* state = (const float*)d_in[1];
    const float* b0    = (const float*)d_in[2];
    const float* b1    = (const float*)d_in[3];
    const float* a1    = (const float*)d_in[4];
    float* out = (float*)d_out;

    long TB = in_sizes[0];
    int  B  = in_sizes[1];
    int  T  = (int)(TB / B);

    bool writeFinal = ((long)out_size >= TB + B);
    float* finalDst = writeFinal ? (out + TB) : nullptr;

    const int TPB = 256;

    if ((B & 1) == 0) {
        int B2 = B >> 1;
        int xBlocks = (B2 + TPB - 1) / TPB;                 // 8 for B=4096
        // choose numChunks so total blocks ~= 4 per SM, L multiple of 8
        int numChunks = (NUM_SMS * 4) / xBlocks;            // 74
        if (numChunks < 1) numChunks = 1;
        if (numChunks > T) numChunks = T;
        int L = (T + numChunks - 1) / numChunks;
        L = (L + 7) & ~7;                                    // 224
        numChunks = (T + L - 1) / L;                         // 74

        dim3 grid(xBlocks, numChunks);
        k_fused2<<<grid, TPB>>>((const float2*)x, (const float2*)state,
                                b0, b1, a1, (float2*)out,
                                (float2*)finalDst, T, B2, L);
    } else {
        int xBlocks = (B + TPB - 1) / TPB;
        int numChunks = (NUM_SMS * 4) / xBlocks;
        if (numChunks < 1) numChunks = 1;
        if (numChunks > T) numChunks = T;
        int L = (T + numChunks - 1) / numChunks;
        L = (L + 7) & ~7;
        numChunks = (T + L - 1) / L;

        dim3 grid(xBlocks, numChunks);
        k_fused1<<<grid, TPB>>>(x, state, b0, b1, a1, out, finalDst, T, B, L);
    }
}

// round 10
// speedup vs baseline: 2.8384x; 1.0441x over previous
#include <cuda_runtime.h>

// ---------------------------------------------------------------------------
// One-pole IIR scan:  out_t = b0*x_t + s_{t-1};  s_t = b1*x_t + a*out_t
// State-only form:    s_t = k*x_t + a*s_{t-1},   k = b1 + a*b0  (a = clamp(a1))
//
// Single fused pass, chunked over time; each chunk warms its state up from
// zero W steps early with |a|^W < 2^-24 (fp32 epsilon; rel-err budget is
// 1e-3, so margin is ~1e5x). W clamps to the chunk start, so the result is
// exact for any |a| (chunk 0 always uses the true initial state).
//
// Execution structure (validated R7): 592 blocks = exactly 4/SM on 148 SMs,
// 256 threads/block, loads explicitly batched 8-at-a-time into register
// arrays (64 B/thread in LSU flight). Scalar elements -> 16 column-blocks,
// 37 chunks, L=443: warmup overhead only 5.6% of read traffic.
// ---------------------------------------------------------------------------

#define NUM_SMS 148

__device__ __forceinline__ float clamp_a(float a) {
    return fminf(fmaxf(a, -1.0f), 1.0f);
}

__device__ __forceinline__ int warmup_len(float a, int t0) {
    float la = fabsf(a);
    int W;
    if (la >= 0.999999f) {
        W = t0;                          // exact: run from t=0
    } else if (la <= 1e-30f) {
        W = 2;
    } else {
        float w = ceilf(24.0f / (-__log2f(la)));
        W = (int)w + 1;
        if (W < 2) W = 2;
    }
    if (W > t0) W = t0;
    return W;
}

__global__ void __launch_bounds__(256, 4)
k_fused(const float* __restrict__ x,
        const float* __restrict__ statep,
        const float* __restrict__ b0p,
        const float* __restrict__ b1p,
        const float* __restrict__ a1p,
        float* __restrict__ out,
        float* __restrict__ finalDst,   // may be null
        int T, int B, int L) {
    int c = blockIdx.x * blockDim.x + threadIdx.x;
    if (c >= B) return;
    int chunk = blockIdx.y;

    float a  = clamp_a(a1p[0]);
    float b0 = b0p[0];
    float k  = fmaf(a, b0, b1p[0]);      // k = b1 + a*b0

    int t0 = chunk * L;
    if (t0 >= T) return;
    int tend = t0 + L; if (tend > T) tend = T;

    int W = warmup_len(a, t0);
    int start = t0 - W;

    float s = (start == 0) ? statep[c] : 0.0f;

    // --- warmup: state-only, batch-8 loads ---
    {
        const float* p = x + (long)start * B + c;
        int nw = t0 - start;
        int nw8 = nw & ~7;
        int i = 0;
        for (; i < nw8; i += 8) {
            float v[8];
            #pragma unroll
            for (int u = 0; u < 8; u++) v[u] = p[(long)(i + u) * B];
            #pragma unroll
            for (int u = 0; u < 8; u++) s = fmaf(a, s, k * v[u]);
        }
        for (; i < nw; i++) s = fmaf(a, s, k * p[(long)i * B]);
    }

    // --- main: batch-8 load / compute / store ---
    {
        const float* pm = x + (long)t0 * B + c;
        float* po = out + (long)t0 * B + c;
        int n = tend - t0;
        int n8 = n & ~7;
        int j = 0;
        for (; j < n8; j += 8) {
            const float* pm8 = pm + (long)j * B;
            float v[8];
            #pragma unroll
            for (int u = 0; u < 8; u++) v[u] = pm8[(long)u * B];
            float o[8];
            #pragma unroll
            for (int u = 0; u < 8; u++) {
                o[u] = fmaf(b0, v[u], s);
                s = fmaf(a, s, k * v[u]);    // s = k*x + a*s
            }
            float* po8 = po + (long)j * B;
            #pragma unroll
            for (int u = 0; u < 8; u++) {
                __stcs(po8, o[u]);
                po8 += B;
            }
        }
        for (; j < n; j++) {
            float v = pm[(long)j * B];
            float o = fmaf(b0, v, s);
            __stcs(&po[(long)j * B], o);
            s = fmaf(a, s, k * v);
        }
    }

    if (finalDst && tend == T) finalDst[c] = s;
}

// ---------------------------------------------------------------------------

extern "C" void kernel_launch(void* const* d_in, const int* in_sizes, int n_in,
                              void* d_out, int out_size) {
    const float* x     = (const float*)d_in[0];
    const float* state = (const float*)d_in[1];
    const float* b0    = (const float*)d_in[2];
    const float* b1    = (const float*)d_in[3];
    const float* a1    = (const float*)d_in[4];
    float* out = (float*)d_out;

    long TB = in_sizes[0];
    int  B  = in_sizes[1];
    int  T  = (int)(TB / B);

    bool writeFinal = ((long)out_size >= TB + B);
    float* finalDst = writeFinal ? (out + TB) : nullptr;

    const int TPB = 256;
    int xBlocks = (B + TPB - 1) / TPB;                 // 16 for B=4096

    // choose numChunks so total blocks ~= 4 per SM (592 on 148 SMs)
    int numChunks = (NUM_SMS * 4) / xBlocks;           // 37
    if (numChunks < 1) numChunks = 1;
    if (numChunks > T) numChunks = T;
    int L = (T + numChunks - 1) / numChunks;           // 443
    numChunks = (T + L - 1) / L;                       // 37

    dim3 grid(xBlocks, numChunks);
    k_fused<<<grid, TPB>>>(x, state, b0, b1, a1, out, finalDst, T, B, L);
}